// round 11
// baseline (speedup 1.0000x reference)
#include <cuda_runtime.h>
#include <cuda_bf16.h>
#include <cstdint>

#define DD     12
#define VOLPB  1728
#define BATCH  512
#define NPTS   442368
#define NVOX   884736
#define BM     128
#define NBLK   3456
#define INVN   (1.0f/442368.0f)
#define BN_EPS 1e-5f

// packed bf16 weight regions (elements)
#define WH0 0
#define WH1 28672
#define WH2 249856
#define WHTOT 471040
// fp32 fallback weight regions
#define WF0 0
#define WF1 27648
#define WF2 248832
#define WFTOT 470016

#if defined(__CUDA_ARCH__) && (defined(__CUDA_ARCH_FEAT_SM103_ALL) || \
    defined(__CUDA_ARCH_FEAT_SM100_ALL) || defined(__CUDA_ARCH_FEAT_SM101_ALL))
#define HAS_TCGEN05 1
#else
#define HAS_TCGEN05 0
#endif

// ---------------- device scratch ----------------
__device__ __align__(256) int            g_map[NVOX];
__device__ __align__(256) int            g_nbr[27 * NPTS];
__device__ __align__(256) float          g_feat[(size_t)NPTS * 128];
__device__ __align__(256) __nv_bfloat16  g_fh[(size_t)NPTS * 128];
__device__ __align__(256) __nv_bfloat16  g_fl[(size_t)NPTS * 128];
__device__ __align__(256) float          g_conv[(size_t)NPTS * 128];
__device__ __align__(256) __nv_bfloat16  g_Wh[WHTOT];
__device__ __align__(256) __nv_bfloat16  g_Wl[WHTOT];
__device__ __align__(256) float          g_Wf[WFTOT];
__device__ __align__(256) float          g_part[NBLK * 128];
__device__ __align__(256) float          g_partsq[NBLK * 128];
__device__ __align__(256) float          g_scale[128];
__device__ __align__(256) float          g_shift[128];

// ---------------- generic helpers ----------------
__device__ __forceinline__ uint32_t smem_u32(const void* p) {
    uint32_t a;
    asm("{ .reg .u64 t; cvta.to.shared.u64 t, %1; cvt.u32.u64 %0, t; }"
        : "=r"(a) : "l"(p));
    return a;
}

#if HAS_TCGEN05
__device__ __forceinline__ bool elect_one() {
    uint32_t pred;
    asm volatile("{\n\t.reg .pred p;\n\telect.sync _|p, 0xFFFFFFFF;\n\t"
                 "selp.b32 %0, 1, 0, p;\n\t}" : "=r"(pred));
    return pred != 0;
}
__device__ __forceinline__ void mbar_init(uint32_t addr, uint32_t cnt) {
    asm volatile("mbarrier.init.shared.b64 [%0], %1;" :: "r"(addr), "r"(cnt)
                 : "memory");
}
__device__ __forceinline__ void mbar_wait(uint32_t addr, uint32_t phase) {
    asm volatile(
        "{\n\t.reg .pred P;\n\t"
        "W%=:\n\t"
        "mbarrier.try_wait.parity.acquire.cta.shared::cta.b64 P, [%0], %1, 0x989680;\n\t"
        "@!P bra W%=;\n\t}"
        :: "r"(addr), "r"(phase) : "memory");
}
__device__ __forceinline__ void tmem_alloc(uint32_t dst_smem, uint32_t ncols) {
    asm volatile("tcgen05.alloc.cta_group::1.sync.aligned.shared::cta.b32 [%0], %1;"
                 :: "r"(dst_smem), "r"(ncols) : "memory");
}
__device__ __forceinline__ void tmem_relinquish() {
    asm volatile("tcgen05.relinquish_alloc_permit.cta_group::1.sync.aligned;");
}
__device__ __forceinline__ void tmem_dealloc(uint32_t base, uint32_t ncols) {
    asm volatile("tcgen05.dealloc.cta_group::1.sync.aligned.b32 %0, %1;"
                 :: "r"(base), "r"(ncols));
}
__device__ __forceinline__ void fence_proxy_async_sc() {
    asm volatile("fence.proxy.async.shared::cta;" ::: "memory");
}
__device__ __forceinline__ void tc_fence_after() {
    asm volatile("tcgen05.fence::after_thread_sync;" ::: "memory");
}
__device__ __forceinline__ void tc_fence_before() {
    asm volatile("tcgen05.fence::before_thread_sync;" ::: "memory");
}
__device__ __forceinline__ void tc_wait_ld() {
    asm volatile("tcgen05.wait::ld.sync.aligned;" ::: "memory");
}
__device__ __forceinline__ void tc_commit(uint32_t mbar) {
    asm volatile(
        "tcgen05.commit.cta_group::1.mbarrier::arrive::one.shared::cluster.b64 [%0];"
        :: "r"(mbar) : "memory");
}
__device__ __forceinline__ void mma_ss_bf16(uint32_t d, uint64_t ad, uint64_t bd,
                                            uint32_t idesc, uint32_t en) {
    asm volatile(
        "{\n\t.reg .pred p;\n\tsetp.ne.u32 p, %4, 0;\n\t"
        "tcgen05.mma.cta_group::1.kind::f16 [%0], %1, %2, %3, {%5,%5,%5,%5}, p;\n\t}"
        :: "r"(d), "l"(ad), "l"(bd), "r"(idesc), "r"(en), "r"(0u) : "memory");
}
__device__ __forceinline__ void ldtm_x32(uint32_t* r, uint32_t addr) {
    asm volatile(
        "tcgen05.ld.sync.aligned.32x32b.x32.b32 "
        "{%0, %1, %2, %3, %4, %5, %6, %7, "
        " %8, %9, %10, %11, %12, %13, %14, %15, "
        " %16, %17, %18, %19, %20, %21, %22, %23, "
        " %24, %25, %26, %27, %28, %29, %30, %31}, [%32];"
        : "=r"(r[0]),  "=r"(r[1]),  "=r"(r[2]),  "=r"(r[3]),
          "=r"(r[4]),  "=r"(r[5]),  "=r"(r[6]),  "=r"(r[7]),
          "=r"(r[8]),  "=r"(r[9]),  "=r"(r[10]), "=r"(r[11]),
          "=r"(r[12]), "=r"(r[13]), "=r"(r[14]), "=r"(r[15]),
          "=r"(r[16]), "=r"(r[17]), "=r"(r[18]), "=r"(r[19]),
          "=r"(r[20]), "=r"(r[21]), "=r"(r[22]), "=r"(r[23]),
          "=r"(r[24]), "=r"(r[25]), "=r"(r[26]), "=r"(r[27]),
          "=r"(r[28]), "=r"(r[29]), "=r"(r[30]), "=r"(r[31])
        : "r"(addr));
}
__device__ __forceinline__ uint64_t mk_desc(uint32_t addr) {
    const uint64_t base = (2ull << 61) | (1ull << 46) | (64ull << 32) | (1ull << 16);
    return base | ((addr >> 4) & 0x3FFF);
}
__device__ __forceinline__ void cp16(uint32_t dst, const void* src, int srcsz) {
    asm volatile("cp.async.cg.shared.global [%0], [%1], 16, %2;"
                 :: "r"(dst), "l"(src), "r"(srcsz) : "memory");
}
__device__ __forceinline__ void cp_mbar_arrive(uint32_t mbar) {
    asm volatile("cp.async.mbarrier.arrive.noinc.shared.b64 [%0];"
                 :: "r"(mbar) : "memory");
}
#else
__device__ __forceinline__ unsigned long long pack_dup(float a) {
    unsigned long long r;
    asm("mov.b64 %0, {%1, %1};" : "=l"(r) : "f"(a));
    return r;
}
__device__ __forceinline__ void fma2(unsigned long long& acc,
                                     unsigned long long a,
                                     unsigned long long b) {
    asm("fma.rn.f32x2 %0, %1, %2, %0;" : "+l"(acc) : "l"(a), "l"(b));
}
__device__ __forceinline__ float2 unpack2(unsigned long long v) {
    float lo, hi;
    asm("mov.b64 {%0, %1}, %2;" : "=f"(lo), "=f"(hi) : "l"(v));
    return make_float2(lo, hi);
}
#endif

// ---------------- prep ----------------
#if !HAS_TCGEN05
template <int CIN, int COUT, int BK, int KCH>
__device__ __forceinline__ void wsplit_fb(const float* __restrict__ W, int idx,
                                          int wfbase) {
    int ci   = idx & 63;
    int rowI = idx >> 6;
    int co   = rowI % COUT;
    int c    = rowI / COUT;
    int off = c / KCH, kc = c % KCH;
    if (ci < BK)
        g_Wf[wfbase + ((size_t)c * BK + ci) * COUT + co] =
            W[((size_t)(off * CIN + kc * 64 + ci)) * COUT + co];
}
#endif

__global__ void prep0_kernel(const float* __restrict__ W0,
                             const float* __restrict__ W1,
                             const float* __restrict__ W2) {
    int i = blockIdx.x * 256 + threadIdx.x;
    if (i < NVOX) g_map[i] = -1;
#if HAS_TCGEN05
    float v = 0.f;
    int dst = -1;
    if (i < WH1) {                       // conv0 packed: 7 chunks x 64ci x 64co
        int ci64 = i & 63;
        int rowI = i >> 6;
        int co = rowI & 63;
        int c  = rowI >> 6;
        int p = ci64 >> 4, ci16 = ci64 & 15;
        int ko = c * 4 + p;
        if (ko < 27) v = W0[((size_t)(ko * 16 + ci16)) * 64 + co];
        dst = WH0 + rowI * 64 + ((((ci64 >> 3) ^ (co & 7)) << 3) | (ci64 & 7));
    } else if (i < WH2) {                // conv1: 27 chunks x 64ci x 128co
        int idx2 = i - WH1;
        int ci = idx2 & 63;
        int rowI = idx2 >> 6;
        int co = rowI & 127;
        int c  = rowI >> 7;
        v = W1[((size_t)(c * 64 + ci)) * 128 + co];
        dst = WH1 + rowI * 64 + ((((ci >> 3) ^ (co & 7)) << 3) | (ci & 7));
    } else if (i < WHTOT) {              // conv2: 54 chunks x 64ci x 64co
        int idx2 = i - WH2;
        int ci = idx2 & 63;
        int rowI = idx2 >> 6;
        int co = rowI & 63;
        int c  = rowI >> 6;
        int off = c >> 1, kc = c & 1;
        v = W2[((size_t)(off * 128 + kc * 64 + ci)) * 64 + co];
        dst = WH2 + rowI * 64 + ((((ci >> 3) ^ (co & 7)) << 3) | (ci & 7));
    }
    if (dst >= 0) {
        __nv_bfloat16 h = __float2bfloat16(v);
        g_Wh[dst] = h;
        g_Wl[dst] = __float2bfloat16(v - __bfloat162float(h));
    }
#else
    if (i < 27 * 64 * 64)            wsplit_fb<16, 64, 16, 1>(W0, i, WF0);
    else if (i < 27*64*64 + 27*64*128)
        wsplit_fb<64, 128, 64, 1>(W1, i - 27*64*64, WF1);
    else if (i < 27*64*64 + 27*64*128 + 54*64*64)
        wsplit_fb<128, 64, 64, 2>(W2, i - 27*64*64 - 27*64*128, WF2);
#endif
}

__global__ void prep1_kernel(const int* __restrict__ idxs,
                             const float* __restrict__ f) {
    int i = blockIdx.x * 256 + threadIdx.x;
    if (i < NPTS) {
        int b = idxs[4*i+0], z = idxs[4*i+1], y = idxs[4*i+2], x = idxs[4*i+3];
        g_map[((b*DD + z)*DD + y)*DD + x] = i;
    }
    float v = f[i];
    __nv_bfloat16 h = __float2bfloat16(v);
    g_fh[i] = h;
    g_fl[i] = __float2bfloat16(v - __bfloat162float(h));
}

__global__ void build_nbr_kernel(const int* __restrict__ idxs) {
    int tid = blockIdx.x * 256 + threadIdx.x;
    int k = tid / NPTS;
    int n = tid - k * NPTS;
    int b = idxs[4*n+0], z = idxs[4*n+1], y = idxs[4*n+2], x = idxs[4*n+3];
    int zz = z + k/9 - 1, yy = y + (k/3)%3 - 1, xx = x + (k%3) - 1;
    int r = -1;
    if ((unsigned)zz < DD && (unsigned)yy < DD && (unsigned)xx < DD)
        r = g_map[((b*DD + zz)*DD + yy)*DD + xx];
    g_nbr[tid] = r;
}

// ---------------- conv ----------------
// warp-specialized: warps 0-6 produce via cp.async, warp 7 issues MMAs.
// item i = (offset-group c = i/TG, tile j = i%TG); K = NSUB*64 per item.
// NST-stage A ring; B double-buffered per chunk, refreshed at j==TG-1.
// Requires TG >= NST (B overwrite safety via ring wait).
template <int CIN, int COUT, int GOFF, int NSUB, int TG, int NCH, int NST>
__global__ void __launch_bounds__(256)
conv_kernel(const float* __restrict__ featF,
            const float* __restrict__ bias,
            int whbase, int wfbase) {
#if HAS_TCGEN05
    static_assert(TG >= NST, "B overwrite safety needs TG >= NST");
    constexpr int TOT    = NCH * TG;
    constexpr int SUBSEG = 8 / GOFF;
    constexpr int ATILE  = 128 * 128;
    constexpr int ASUB   = 2 * ATILE;        // hi+lo per 64-K sub
    constexpr int ASTG   = NSUB * ASUB;      // per ring stage
    constexpr int BT     = COUT * 128;       // bytes per half per sub
    constexpr int BSZ    = NSUB * 2 * BT;    // one B buffer
    constexpr int CPW    = COUT / 2;
    constexpr uint32_t IDESC =
        (1u << 4) | (1u << 7) | (1u << 10) | ((COUT / 8) << 17) | (8u << 24);

    extern __shared__ __align__(16) char dsm_raw[];
    __shared__ __align__(8) unsigned long long s_full[NST], s_cmt[NST];
    __shared__ uint32_t s_tmem;
    __shared__ float sP[4][128], sQ[4][128];

    char* smp = (char*)((((uintptr_t)dsm_raw) + 1023) & ~(uintptr_t)1023);
    const uint32_t smu   = smem_u32(smp);
    const uint32_t aBase = smu;
    const uint32_t bBase = smu + NST * ASTG;

    const int t    = threadIdx.x;
    const int wid  = t >> 5;
    const int lane = t & 31;

    if (wid == 0) {
        tmem_alloc(smem_u32(&s_tmem), TG * COUT);   // 512 cols, 1 CTA/SM
        tmem_relinquish();
    }
    if (t == 0) {
        #pragma unroll
        for (int s = 0; s < NST; ++s) {
            mbar_init(smem_u32(&s_full[s]), 224);
            mbar_init(smem_u32(&s_cmt[s]), 1);
        }
    }
    __syncthreads();
    const uint32_t tmem = s_tmem;
    uint32_t fmb[NST], cmb[NST];
    #pragma unroll
    for (int s = 0; s < NST; ++s) {
        fmb[s] = smem_u32(&s_full[s]);
        cmb[s] = smem_u32(&s_cmt[s]);
    }

    const int tileBase = blockIdx.x * TG;

    if (wid < 7) {
        // ======================= PRODUCERS =======================
        const char* whp = (const char*)(g_Wh + whbase);
        const char* wlp = (const char*)(g_Wl + whbase);
        uint32_t cph[NST];
        int      cws[NST];
        #pragma unroll
        for (int s = 0; s < NST; ++s) { cph[s] = 0u; cws[s] = s; }

        auto wait_until = [&](int slot, int target) {
            while (cws[slot] <= target) {
                mbar_wait(cmb[slot], cph[slot]);
                cph[slot] ^= 1;
                cws[slot] += NST;
            }
        };

        int nb[2][GOFF];
        auto prefetch = [&](int i) {
            const int c = i / TG, j = i - (i / TG) * TG;
            #pragma unroll
            for (int k = 0; k < 2; ++k) {
                int u = t + k * 224;
                if (u < 256) {
                    int row = u >> 1;
                    #pragma unroll
                    for (int p = 0; p < GOFF; ++p) {
                        int ko = c * GOFF + p;
                        nb[k][p] = (ko < 27)
                            ? g_nbr[ko * NPTS + (tileBase + j) * BM + row] : -1;
                    }
                }
            }
        };

        auto fill_B = [&](int c2) {   // chunk c2 into buffer c2&1
            const uint32_t bb = bBase + (c2 & 1) * BSZ;
            #pragma unroll
            for (int sub = 0; sub < NSUB; ++sub) {
                const char* sh = whp + (size_t)(c2 * NSUB + sub) * BT;
                const char* sl = wlp + (size_t)(c2 * NSUB + sub) * BT;
                const uint32_t d0 = bb + sub * 2 * BT;
                for (int q = t; q < BT / 16; q += 224) {
                    cp16(d0 + q * 16,      sh + q * 16, 16);
                    cp16(d0 + BT + q * 16, sl + q * 16, 16);
                }
            }
        };

        prefetch(0);
        #pragma unroll 1
        for (int i = 0; i < TOT; ++i) {
            const int c = i / TG, j = i - c * TG;
            const int s = i % NST;

            wait_until(s, i - NST);
            if (i == 0) fill_B(0);

            // A gathers into stage s
            #pragma unroll
            for (int k = 0; k < 2; ++k) {
                int u = t + k * 224;
                if (u < 256) {
                    const int row = u >> 1, half = u & 1;
                    const __nv_bfloat16* fp = half ? g_fl : g_fh;
                    #pragma unroll
                    for (int sub = 0; sub < NSUB; ++sub) {
                        const uint32_t dst = aBase + s * ASTG + sub * ASUB +
                                             half * ATILE + row * 128;
                        #pragma unroll
                        for (int p = 0; p < GOFF; ++p) {
                            const int nbv = nb[k][p];
                            const char* src = (const char*)
                                (fp + (size_t)(nbv < 0 ? 0 : nbv) * CIN
                                    + sub * 64);
                            const int sz = nbv >= 0 ? 16 : 0;
                            #pragma unroll
                            for (int s2 = 0; s2 < SUBSEG; ++s2) {
                                int g = p * SUBSEG + s2;
                                cp16(dst + (((g ^ (row & 7)) << 4)),
                                     src + s2 * 16, sz);
                            }
                        }
                    }
                }
            }
            // refresh next chunk's B at last tile of this chunk
            // (safe: ring wait gave commit(i-NST) >= commit(c*TG-1) since TG>=NST)
            if (j == TG - 1 && c + 1 < NCH) fill_B(c + 1);

            cp_mbar_arrive(fmb[s]);
            if (i + 1 < TOT) prefetch(i + 1);
        }
        #pragma unroll
        for (int s = 0; s < NST; ++s) wait_until(s, TOT - 1);
    } else {
        // ======================= CONSUMER (warp 7) =======================
        uint32_t fph[NST];
        #pragma unroll
        for (int s = 0; s < NST; ++s) fph[s] = 0u;
        #pragma unroll 1
        for (int i = 0; i < TOT; ++i) {
            const int c = i / TG, j = i - c * TG;
            const int s = i % NST;
            mbar_wait(fmb[s], fph[s]);
            fph[s] ^= 1;
            fence_proxy_async_sc();
            tc_fence_after();
            if (elect_one()) {
                const uint32_t bb  = bBase + (c & 1) * BSZ;
                const uint32_t dTm = tmem + (uint32_t)(j * COUT);
                #pragma unroll
                for (int sub = 0; sub < NSUB; ++sub) {
                    const uint32_t ab = aBase + s * ASTG + sub * ASUB;
                    uint64_t dAh = mk_desc(ab);
                    uint64_t dAl = mk_desc(ab + ATILE);
                    uint64_t dBh = mk_desc(bb + sub * 2 * BT);
                    uint64_t dBl = mk_desc(bb + sub * 2 * BT + BT);
                    #pragma unroll
                    for (int ks = 0; ks < 4; ++ks)
                        mma_ss_bf16(dTm, dAh + ks * 2, dBh + ks * 2, IDESC,
                                    (c == 0 && sub == 0 && ks == 0) ? 0u : 1u);
                    #pragma unroll
                    for (int ks = 0; ks < 4; ++ks)
                        mma_ss_bf16(dTm, dAh + ks * 2, dBl + ks * 2, IDESC, 1u);
                    #pragma unroll
                    for (int ks = 0; ks < 4; ++ks)
                        mma_ss_bf16(dTm, dAl + ks * 2, dBh + ks * 2, IDESC, 1u);
                }
                tc_commit(cmb[s]);
            }
        }
    }

    __syncthreads();
    tc_fence_after();

    // ---------------- epilogue ----------------
    const int grp     = wid >> 2;
    const int rw      = wid & 3;
    const int colBase = grp * CPW;

    for (int j = 0; j < TG; ++j) {
        const int tile = tileBase + j;
        const int row  = tile * BM + rw * 32 + lane;
        #pragma unroll
        for (int p = 0; p < CPW / 32; ++p) {
            uint32_t dr[32];
            ldtm_x32(dr, tmem + (uint32_t)(j * COUT + colBase + p * 32));
            tc_wait_ld();
            #pragma unroll
            for (int jj = 0; jj < 32; jj += 4) {
                float y[4];
                #pragma unroll
                for (int q = 0; q < 4; ++q) {
                    int col = colBase + p * 32 + jj + q;
                    y[q] = __uint_as_float(dr[jj + q]) + __ldg(bias + col);
                    float s = y[q], qq = y[q] * y[q];
                    #pragma unroll
                    for (int o = 16; o; o >>= 1) {
                        s  += __shfl_xor_sync(0xffffffffu, s, o);
                        qq += __shfl_xor_sync(0xffffffffu, qq, o);
                    }
                    if (lane == (col & 31)) {
                        sP[rw][col] = s;
                        sQ[rw][col] = qq;
                    }
                }
                *(float4*)(&g_conv[(size_t)row * COUT + colBase + p * 32 + jj]) =
                    make_float4(y[0], y[1], y[2], y[3]);
            }
        }
        __syncthreads();
        if (t < COUT) {
            g_part[(size_t)tile * COUT + t] =
                sP[0][t] + sP[1][t] + sP[2][t] + sP[3][t];
            g_partsq[(size_t)tile * COUT + t] =
                sQ[0][t] + sQ[1][t] + sQ[2][t] + sQ[3][t];
        }
        __syncthreads();
    }
    tc_fence_before();
    __syncthreads();
    if (wid == 0) tmem_dealloc(tmem, TG * COUT);

#else  // ------------------- scalar FFMA fallback -------------
    constexpr int BK   = (CIN < 64) ? CIN : 64;
    constexpr int KCH  = NSUB;
    constexpr int TN   = COUT / 16;
    constexpr int SEGS = BK / 4;

    extern __shared__ __align__(16) float sm[];
    float* As = sm;
    float* Bs = sm + BK * BM;
    __shared__ int sN[BM];

    const int t  = threadIdx.x;
    const int tr = t >> 4;
    const int tc = t & 15;

    for (int tile = blockIdx.x * TG; tile < (blockIdx.x + 1) * TG; ++tile) {
        const int rowBase = tile * BM;

        unsigned long long acc[8][TN/2];
        #pragma unroll
        for (int i = 0; i < 8; i++)
            #pragma unroll
            for (int j = 0; j < TN/2; j++) acc[i][j] = 0ull;

        for (int k = 0; k < 27; k++) {
            __syncthreads();
            if (t < BM) sN[t] = g_nbr[k * NPTS + rowBase + t];
            __syncthreads();
            #pragma unroll
            for (int kc = 0; kc < KCH; kc++) {
                if (kc) __syncthreads();
                #pragma unroll
                for (int f = t; f < BM * SEGS; f += 256) {
                    int row = f / SEGS;
                    int seg = f - row * SEGS;
                    int nb  = sN[row];
                    float4 v = make_float4(0.f, 0.f, 0.f, 0.f);
                    if (nb >= 0)
                        v = *reinterpret_cast<const float4*>(
                            featF + (size_t)nb * CIN + kc * BK + seg * 4);
                    int rs = row ^ ((seg & 3) << 3);
                    As[(seg*4+0)*BM + rs] = v.x;
                    As[(seg*4+1)*BM + rs] = v.y;
                    As[(seg*4+2)*BM + rs] = v.z;
                    As[(seg*4+3)*BM + rs] = v.w;
                }
                const float4* Wk = (const float4*)(
                    g_Wf + wfbase + ((size_t)(k * KCH + kc)) * BK * COUT);
                #pragma unroll
                for (int f = t; f < BK * COUT / 4; f += 256)
                    reinterpret_cast<float4*>(Bs)[f] = Wk[f];
                __syncthreads();
                #pragma unroll 8
                for (int kk = 0; kk < BK; kk++) {
                    int rbase = (tr * 8) ^ (((kk >> 2) & 3) << 3);
                    float4 a0 = *reinterpret_cast<const float4*>(&As[kk*BM + rbase]);
                    float4 a1 = *reinterpret_cast<const float4*>(&As[kk*BM + rbase + 4]);
                    unsigned long long ad[8];
                    ad[0] = pack_dup(a0.x); ad[1] = pack_dup(a0.y);
                    ad[2] = pack_dup(a0.z); ad[3] = pack_dup(a0.w);
                    ad[4] = pack_dup(a1.x); ad[5] = pack_dup(a1.y);
                    ad[6] = pack_dup(a1.z); ad[7] = pack_dup(a1.w);
                    unsigned long long bb[TN/2];
                    const ulonglong2* bp = reinterpret_cast<const ulonglong2*>(
                        &Bs[kk * COUT + tc * TN]);
                    {
                        ulonglong2 b0 = bp[0];
                        bb[0] = b0.x; bb[1] = b0.y;
                        if constexpr (TN == 8) {
                            ulonglong2 b1 = bp[1];
                            bb[2] = b1.x; bb[3] = b1.y;
                        }
                    }
                    #pragma unroll
                    for (int i = 0; i < 8; i++)
                        #pragma unroll
                        for (int j = 0; j < TN/2; j++)
                            fma2(acc[i][j], ad[i], bb[j]);
                }
            }
        }

        float bv[TN];
        #pragma unroll
        for (int j = 0; j < TN; j++) bv[j] = bias[tc * TN + j];
        float cs[TN], cq[TN];
        #pragma unroll
        for (int j = 0; j < TN; j++) { cs[j] = 0.f; cq[j] = 0.f; }

        #pragma unroll
        for (int i = 0; i < 8; i++) {
            float yv[TN];
            #pragma unroll
            for (int j = 0; j < TN/2; j++) {
                float2 p = unpack2(acc[i][j]);
                yv[2*j]   = p.x + bv[2*j];
                yv[2*j+1] = p.y + bv[2*j+1];
            }
            #pragma unroll
            for (int j = 0; j < TN; j++) { cs[j] += yv[j]; cq[j] += yv[j]*yv[j]; }
            int row = rowBase + tr * 8 + i;
            #pragma unroll
            for (int j = 0; j < TN; j += 4) {
                float4 o = make_float4(yv[j], yv[j+1], yv[j+2], yv[j+3]);
                *reinterpret_cast<float4*>(
                    &g_conv[(size_t)row * COUT + tc * TN + j]) = o;
            }
        }

        __syncthreads();
        #pragma unroll
        for (int j = 0; j < TN; j++) As[tr * COUT + tc * TN + j] = cs[j];
        __syncthreads();
        if (t < COUT) {
            float s = 0.f;
            #pragma unroll
            for (int rr = 0; rr < 16; rr++) s += As[rr * COUT + t];
            g_part[(size_t)tile * COUT + t] = s;
        }
        __syncthreads();
        #pragma unroll
        for (int j = 0; j < TN; j++) As[tr * COUT + tc * TN + j] = cq[j];
        __syncthreads();
        if (t < COUT) {
            float s = 0.f;
            #pragma unroll
            for (int rr = 0; rr < 16; rr++) s += As[rr * COUT + t];
            g_partsq[(size_t)tile * COUT + t] = s;
        }
        __syncthreads();
    }
#endif
}

// ---------------- BN statistics ----------------
__global__ void bn_reduce_kernel(const float* __restrict__ gamma,
                                 const float* __restrict__ beta, int cout) {
    __shared__ float ss[256], sq[256];
    int c = blockIdx.x;
    int t = threadIdx.x;
    float s = 0.f, q = 0.f;
    for (int b = t; b < NBLK; b += 256) {
        s += g_part[b * cout + c];
        q += g_partsq[b * cout + c];
    }
    ss[t] = s; sq[t] = q;
    __syncthreads();
    for (int o = 128; o > 0; o >>= 1) {
        if (t < o) { ss[t] += ss[t + o]; sq[t] += sq[t + o]; }
        __syncthreads();
    }
    if (t == 0) {
        float mean = ss[0] * INVN;
        float var  = sq[0] * INVN - mean * mean;
        float sc   = gamma[c] * rsqrtf(var + BN_EPS);
        g_scale[c] = sc;
        g_shift[c] = beta[c] - mean * sc;
    }
}

// ---------------- BN apply + ReLU ----------------
template <int COUT>
__global__ void bnrelu_kernel() {
    int i = blockIdx.x * 256 + threadIdx.x;
    int c = i & (COUT - 1);
    float v = fmaf(g_conv[i], g_scale[c], g_shift[c]);
    v = v > 0.f ? v : 0.f;
#if !HAS_TCGEN05
    g_feat[i] = v;
#endif
    __nv_bfloat16 h = __float2bfloat16(v);
    g_fh[i] = h;
    g_fl[i] = __float2bfloat16(v - __bfloat162float(h));
}

// ---------------- final dense scatter ----------------
__global__ void final_out_kernel(float* __restrict__ out) {
    int idx = blockIdx.x * 256 + threadIdx.x;
    int lin = idx % VOLPB;
    int bc  = idx / VOLPB;
    int c = bc & 63;
    int b = bc >> 6;
    int row = g_map[b * VOLPB + lin];
    float v = 0.f;
    if (row >= 0) {
        float y = fmaf(g_conv[(size_t)row * 64 + c], g_scale[c], g_shift[c]);
        v = y > 0.f ? y : 0.f;
    }
    out[idx] = v;
}

// ---------------- launch ----------------
extern "C" void kernel_launch(void* const* d_in, const int* in_sizes, int n_in,
                              void* d_out, int out_size) {
    (void)in_sizes; (void)out_size;
    int base = (n_in >= 15) ? 3 : 2;
    const float* features = (const float*)d_in[0];
    const int*   indices  = (const int*)d_in[1];
    const float* W0  = (const float*)d_in[base + 0];
    const float* b0  = (const float*)d_in[base + 1];
    const float* ga0 = (const float*)d_in[base + 2];
    const float* be0 = (const float*)d_in[base + 3];
    const float* W1  = (const float*)d_in[base + 4];
    const float* b1  = (const float*)d_in[base + 5];
    const float* ga1 = (const float*)d_in[base + 6];
    const float* be1 = (const float*)d_in[base + 7];
    const float* W2  = (const float*)d_in[base + 8];
    const float* b2  = (const float*)d_in[base + 9];
    const float* ga2 = (const float*)d_in[base + 10];
    const float* be2 = (const float*)d_in[base + 11];
    float* out = (float*)d_out;

    float* featp = nullptr;
    cudaGetSymbolAddress((void**)&featp, g_feat);

    // smem: NST*NSUB*32KB (A ring) + 2*NSUB*2*COUT*128 (B dbl buf) + 1KB pad
    constexpr int SMC0 = 4 * 1 * 32768 + 2 * (1 * 2 * 64  * 128) + 1024; // 164KB
    constexpr int SMC1 = 4 * 1 * 32768 + 2 * (1 * 2 * 128 * 128) + 1024; // 197KB
    constexpr int SMC2 = 2 * 2 * 32768 + 2 * (2 * 2 * 64  * 128) + 1024; // 197KB
    cudaFuncSetAttribute(conv_kernel<16, 64, 4, 1, 8, 7, 4>,
                         cudaFuncAttributeMaxDynamicSharedMemorySize, SMC0);
    cudaFuncSetAttribute(conv_kernel<64, 128, 1, 1, 4, 27, 4>,
                         cudaFuncAttributeMaxDynamicSharedMemorySize, SMC1);
    cudaFuncSetAttribute(conv_kernel<128, 64, 1, 2, 8, 27, 2>,
                         cudaFuncAttributeMaxDynamicSharedMemorySize, SMC2);

    prep0_kernel<<<NVOX / 256, 256>>>(W0, W1, W2);
    prep1_kernel<<<NPTS * 16 / 256, 256>>>(indices, features);
    build_nbr_kernel<<<27 * NPTS / 256, 256>>>(indices);

    // layer 0: 16 -> 64 (TG=8 -> 432 CTAs, 56 items)
    conv_kernel<16, 64, 4, 1, 8, 7, 4><<<NBLK / 8, 256, SMC0>>>(
        features, b0, WH0, WF0);
    bn_reduce_kernel<<<64, 256>>>(ga0, be0, 64);
    bnrelu_kernel<64><<<NPTS * 64 / 256, 256>>>();

    // layer 1: 64 -> 128 (TG=4 -> 864 CTAs, 108 items)
    conv_kernel<64, 128, 1, 1, 4, 27, 4><<<NBLK / 4, 256, SMC1>>>(
        featp, b1, WH1, WF1);
    bn_reduce_kernel<<<128, 256>>>(ga1, be1, 128);
    bnrelu_kernel<128><<<NPTS * 128 / 256, 256>>>();

    // layer 2: 128 -> 64 (TG=8 -> 432 CTAs, 216 items of K=128)
    conv_kernel<128, 64, 1, 2, 8, 27, 2><<<NBLK / 8, 256, SMC2>>>(
        featp, b2, WH2, WF2);
    bn_reduce_kernel<<<64, 256>>>(ga2, be2, 64);

    final_out_kernel<<<(BATCH * 64 * VOLPB) / 256, 256>>>(out);
}

// round 12
// speedup vs baseline: 1.0278x; 1.0278x over previous
#include <cuda_runtime.h>
#include <cuda_bf16.h>
#include <cstdint>

#define DD     12
#define VOLPB  1728
#define BATCH  512
#define NPTS   442368
#define NVOX   884736
#define BM     128
#define NBLK   3456
#define INVN   (1.0f/442368.0f)
#define BN_EPS 1e-5f

// packed bf16 weight regions (elements)
#define WH0 0
#define WH1 28672
#define WH2 249856
#define WHTOT 471040
// fp32 fallback weight regions
#define WF0 0
#define WF1 27648
#define WF2 248832
#define WFTOT 470016

#if defined(__CUDA_ARCH__) && (defined(__CUDA_ARCH_FEAT_SM103_ALL) || \
    defined(__CUDA_ARCH_FEAT_SM100_ALL) || defined(__CUDA_ARCH_FEAT_SM101_ALL))
#define HAS_TCGEN05 1
#else
#define HAS_TCGEN05 0
#endif

// ---------------- device scratch ----------------
__device__ __align__(256) int            g_map[NVOX];
__device__ __align__(256) int            g_nbr[27 * NPTS];
__device__ __align__(256) float          g_feat[(size_t)NPTS * 128];
__device__ __align__(256) __nv_bfloat16  g_fh[(size_t)NPTS * 128];
__device__ __align__(256) __nv_bfloat16  g_fl[(size_t)NPTS * 128];
__device__ __align__(256) float          g_conv[(size_t)NPTS * 128];
__device__ __align__(256) __nv_bfloat16  g_Wh[WHTOT];
__device__ __align__(256) __nv_bfloat16  g_Wl[WHTOT];
__device__ __align__(256) float          g_Wf[WFTOT];
__device__ __align__(256) float          g_part[NBLK * 128];
__device__ __align__(256) float          g_partsq[NBLK * 128];
__device__ __align__(256) float          g_scale[128];
__device__ __align__(256) float          g_shift[128];

// ---------------- generic helpers ----------------
__device__ __forceinline__ uint32_t smem_u32(const void* p) {
    uint32_t a;
    asm("{ .reg .u64 t; cvta.to.shared.u64 t, %1; cvt.u32.u64 %0, t; }"
        : "=r"(a) : "l"(p));
    return a;
}

#if HAS_TCGEN05
__device__ __forceinline__ bool elect_one() {
    uint32_t pred;
    asm volatile("{\n\t.reg .pred p;\n\telect.sync _|p, 0xFFFFFFFF;\n\t"
                 "selp.b32 %0, 1, 0, p;\n\t}" : "=r"(pred));
    return pred != 0;
}
__device__ __forceinline__ void mbar_init(uint32_t addr, uint32_t cnt) {
    asm volatile("mbarrier.init.shared.b64 [%0], %1;" :: "r"(addr), "r"(cnt)
                 : "memory");
}
__device__ __forceinline__ void mbar_wait(uint32_t addr, uint32_t phase) {
    asm volatile(
        "{\n\t.reg .pred P;\n\t"
        "W%=:\n\t"
        "mbarrier.try_wait.parity.acquire.cta.shared::cta.b64 P, [%0], %1, 0x989680;\n\t"
        "@!P bra W%=;\n\t}"
        :: "r"(addr), "r"(phase) : "memory");
}
__device__ __forceinline__ void tmem_alloc(uint32_t dst_smem, uint32_t ncols) {
    asm volatile("tcgen05.alloc.cta_group::1.sync.aligned.shared::cta.b32 [%0], %1;"
                 :: "r"(dst_smem), "r"(ncols) : "memory");
}
__device__ __forceinline__ void tmem_relinquish() {
    asm volatile("tcgen05.relinquish_alloc_permit.cta_group::1.sync.aligned;");
}
__device__ __forceinline__ void tmem_dealloc(uint32_t base, uint32_t ncols) {
    asm volatile("tcgen05.dealloc.cta_group::1.sync.aligned.b32 %0, %1;"
                 :: "r"(base), "r"(ncols));
}
__device__ __forceinline__ void fence_proxy_async_sc() {
    asm volatile("fence.proxy.async.shared::cta;" ::: "memory");
}
__device__ __forceinline__ void tc_fence_after() {
    asm volatile("tcgen05.fence::after_thread_sync;" ::: "memory");
}
__device__ __forceinline__ void tc_fence_before() {
    asm volatile("tcgen05.fence::before_thread_sync;" ::: "memory");
}
__device__ __forceinline__ void tc_wait_ld() {
    asm volatile("tcgen05.wait::ld.sync.aligned;" ::: "memory");
}
__device__ __forceinline__ void tc_commit(uint32_t mbar) {
    asm volatile(
        "tcgen05.commit.cta_group::1.mbarrier::arrive::one.shared::cluster.b64 [%0];"
        :: "r"(mbar) : "memory");
}
__device__ __forceinline__ void mma_ss_bf16(uint32_t d, uint64_t ad, uint64_t bd,
                                            uint32_t idesc, uint32_t en) {
    asm volatile(
        "{\n\t.reg .pred p;\n\tsetp.ne.u32 p, %4, 0;\n\t"
        "tcgen05.mma.cta_group::1.kind::f16 [%0], %1, %2, %3, {%5,%5,%5,%5}, p;\n\t}"
        :: "r"(d), "l"(ad), "l"(bd), "r"(idesc), "r"(en), "r"(0u) : "memory");
}
__device__ __forceinline__ void ldtm_x32(uint32_t* r, uint32_t addr) {
    asm volatile(
        "tcgen05.ld.sync.aligned.32x32b.x32.b32 "
        "{%0, %1, %2, %3, %4, %5, %6, %7, "
        " %8, %9, %10, %11, %12, %13, %14, %15, "
        " %16, %17, %18, %19, %20, %21, %22, %23, "
        " %24, %25, %26, %27, %28, %29, %30, %31}, [%32];"
        : "=r"(r[0]),  "=r"(r[1]),  "=r"(r[2]),  "=r"(r[3]),
          "=r"(r[4]),  "=r"(r[5]),  "=r"(r[6]),  "=r"(r[7]),
          "=r"(r[8]),  "=r"(r[9]),  "=r"(r[10]), "=r"(r[11]),
          "=r"(r[12]), "=r"(r[13]), "=r"(r[14]), "=r"(r[15]),
          "=r"(r[16]), "=r"(r[17]), "=r"(r[18]), "=r"(r[19]),
          "=r"(r[20]), "=r"(r[21]), "=r"(r[22]), "=r"(r[23]),
          "=r"(r[24]), "=r"(r[25]), "=r"(r[26]), "=r"(r[27]),
          "=r"(r[28]), "=r"(r[29]), "=r"(r[30]), "=r"(r[31])
        : "r"(addr));
}
__device__ __forceinline__ uint64_t mk_desc(uint32_t addr) {
    const uint64_t base = (2ull << 61) | (1ull << 46) | (64ull << 32) | (1ull << 16);
    return base | ((addr >> 4) & 0x3FFF);
}
__device__ __forceinline__ void cp16(uint32_t dst, const void* src, int srcsz) {
    asm volatile("cp.async.cg.shared.global [%0], [%1], 16, %2;"
                 :: "r"(dst), "l"(src), "r"(srcsz) : "memory");
}
__device__ __forceinline__ void cp_mbar_arrive(uint32_t mbar) {
    asm volatile("cp.async.mbarrier.arrive.noinc.shared.b64 [%0];"
                 :: "r"(mbar) : "memory");
}
#else
__device__ __forceinline__ unsigned long long pack_dup(float a) {
    unsigned long long r;
    asm("mov.b64 %0, {%1, %1};" : "=l"(r) : "f"(a));
    return r;
}
__device__ __forceinline__ void fma2(unsigned long long& acc,
                                     unsigned long long a,
                                     unsigned long long b) {
    asm("fma.rn.f32x2 %0, %1, %2, %0;" : "+l"(acc) : "l"(a), "l"(b));
}
__device__ __forceinline__ float2 unpack2(unsigned long long v) {
    float lo, hi;
    asm("mov.b64 {%0, %1}, %2;" : "=f"(lo), "=f"(hi) : "l"(v));
    return make_float2(lo, hi);
}
#endif

// ---------------- prep ----------------
#if !HAS_TCGEN05
template <int CIN, int COUT, int BK, int KCH>
__device__ __forceinline__ void wsplit_fb(const float* __restrict__ W, int idx,
                                          int wfbase) {
    int ci   = idx & 63;
    int rowI = idx >> 6;
    int co   = rowI % COUT;
    int c    = rowI / COUT;
    int off = c / KCH, kc = c % KCH;
    if (ci < BK)
        g_Wf[wfbase + ((size_t)c * BK + ci) * COUT + co] =
            W[((size_t)(off * CIN + kc * 64 + ci)) * COUT + co];
}
#endif

__global__ void prep0_kernel(const float* __restrict__ W0,
                             const float* __restrict__ W1,
                             const float* __restrict__ W2) {
    int i = blockIdx.x * 256 + threadIdx.x;
    if (i < NVOX) g_map[i] = -1;
#if HAS_TCGEN05
    float v = 0.f;
    int dst = -1;
    if (i < WH1) {                       // conv0 packed: 7 chunks x 64ci x 64co
        int ci64 = i & 63;
        int rowI = i >> 6;
        int co = rowI & 63;
        int c  = rowI >> 6;
        int p = ci64 >> 4, ci16 = ci64 & 15;
        int ko = c * 4 + p;
        if (ko < 27) v = W0[((size_t)(ko * 16 + ci16)) * 64 + co];
        dst = WH0 + rowI * 64 + ((((ci64 >> 3) ^ (co & 7)) << 3) | (ci64 & 7));
    } else if (i < WH2) {                // conv1: 27 chunks x 64ci x 128co
        int idx2 = i - WH1;
        int ci = idx2 & 63;
        int rowI = idx2 >> 6;
        int co = rowI & 127;
        int c  = rowI >> 7;
        v = W1[((size_t)(c * 64 + ci)) * 128 + co];
        dst = WH1 + rowI * 64 + ((((ci >> 3) ^ (co & 7)) << 3) | (ci & 7));
    } else if (i < WHTOT) {              // conv2: 54 chunks x 64ci x 64co
        int idx2 = i - WH2;
        int ci = idx2 & 63;
        int rowI = idx2 >> 6;
        int co = rowI & 63;
        int c  = rowI >> 6;
        int off = c >> 1, kc = c & 1;
        v = W2[((size_t)(off * 128 + kc * 64 + ci)) * 64 + co];
        dst = WH2 + rowI * 64 + ((((ci >> 3) ^ (co & 7)) << 3) | (ci & 7));
    }
    if (dst >= 0) {
        __nv_bfloat16 h = __float2bfloat16(v);
        g_Wh[dst] = h;
        g_Wl[dst] = __float2bfloat16(v - __bfloat162float(h));
    }
#else
    if (i < 27 * 64 * 64)            wsplit_fb<16, 64, 16, 1>(W0, i, WF0);
    else if (i < 27*64*64 + 27*64*128)
        wsplit_fb<64, 128, 64, 1>(W1, i - 27*64*64, WF1);
    else if (i < 27*64*64 + 27*64*128 + 54*64*64)
        wsplit_fb<128, 64, 64, 2>(W2, i - 27*64*64 - 27*64*128, WF2);
#endif
}

__global__ void prep1_kernel(const int* __restrict__ idxs,
                             const float* __restrict__ f) {
    int i = blockIdx.x * 256 + threadIdx.x;
    if (i < NPTS) {
        int b = idxs[4*i+0], z = idxs[4*i+1], y = idxs[4*i+2], x = idxs[4*i+3];
        g_map[((b*DD + z)*DD + y)*DD + x] = i;
    }
    float v = f[i];
    __nv_bfloat16 h = __float2bfloat16(v);
    g_fh[i] = h;
    g_fl[i] = __float2bfloat16(v - __bfloat162float(h));
}

__global__ void build_nbr_kernel(const int* __restrict__ idxs) {
    int tid = blockIdx.x * 256 + threadIdx.x;
    int k = tid / NPTS;
    int n = tid - k * NPTS;
    int b = idxs[4*n+0], z = idxs[4*n+1], y = idxs[4*n+2], x = idxs[4*n+3];
    int zz = z + k/9 - 1, yy = y + (k/3)%3 - 1, xx = x + (k%3) - 1;
    int r = -1;
    if ((unsigned)zz < DD && (unsigned)yy < DD && (unsigned)xx < DD)
        r = g_map[((b*DD + zz)*DD + yy)*DD + xx];
    g_nbr[tid] = r;
}

// ---------------- conv ----------------
// warp-specialized: warps 0-6 produce via cp.async, warp 7 issues MMAs.
// item i = (chunk c = i/TG, tile j = i%TG); each item is one K=64 MMA batch.
// chunk c -> offsets (c/KSPL)*GOFF + p  (p<GOFF), channel slice (c%KSPL)*64.
// NST-stage A ring. BDBL: B double-buffered, refreshed at j==TG-1 (needs
// TG>=NST); else B single-buffered with a drain at each chunk start.
template <int CIN, int COUT, int GOFF, int KSPL, int TG, int NCH, int NST,
          bool BDBL>
__global__ void __launch_bounds__(256)
conv_kernel(const float* __restrict__ featF,
            const float* __restrict__ bias,
            int whbase, int wfbase) {
#if HAS_TCGEN05
    static_assert(!BDBL || TG >= NST, "B dbl safety needs TG >= NST");
    constexpr int TOT    = NCH * TG;
    constexpr int SUBSEG = 8 / GOFF;
    constexpr int ATILE  = 128 * 128;
    constexpr int ASTG   = 2 * ATILE;        // hi+lo per stage
    constexpr int BT     = COUT * 128;       // bytes per half per chunk
    constexpr int BSZ    = 2 * BT;           // one B buffer (hi+lo)
    constexpr int CPW    = COUT / 2;
    constexpr uint32_t IDESC =
        (1u << 4) | (1u << 7) | (1u << 10) | ((COUT / 8) << 17) | (8u << 24);

    extern __shared__ __align__(16) char dsm_raw[];
    __shared__ __align__(8) unsigned long long s_full[NST], s_cmt[NST];
    __shared__ uint32_t s_tmem;
    __shared__ float sP[4][128], sQ[4][128];

    char* smp = (char*)((((uintptr_t)dsm_raw) + 1023) & ~(uintptr_t)1023);
    const uint32_t smu   = smem_u32(smp);
    const uint32_t aBase = smu;
    const uint32_t bBase = smu + NST * ASTG;

    const int t    = threadIdx.x;
    const int wid  = t >> 5;
    const int lane = t & 31;

    if (wid == 0) {
        tmem_alloc(smem_u32(&s_tmem), TG * COUT);   // 256 cols: 2 CTAs/SM
        tmem_relinquish();
    }
    if (t == 0) {
        #pragma unroll
        for (int s = 0; s < NST; ++s) {
            mbar_init(smem_u32(&s_full[s]), 224);
            mbar_init(smem_u32(&s_cmt[s]), 1);
        }
    }
    __syncthreads();
    const uint32_t tmem = s_tmem;
    uint32_t fmb[NST], cmb[NST];
    #pragma unroll
    for (int s = 0; s < NST; ++s) {
        fmb[s] = smem_u32(&s_full[s]);
        cmb[s] = smem_u32(&s_cmt[s]);
    }

    const int tileBase = blockIdx.x * TG;

    if (wid < 7) {
        // ======================= PRODUCERS =======================
        const char* whp = (const char*)(g_Wh + whbase);
        const char* wlp = (const char*)(g_Wl + whbase);
        uint32_t cph[NST];
        int      cws[NST];
        #pragma unroll
        for (int s = 0; s < NST; ++s) { cph[s] = 0u; cws[s] = s; }

        auto wait_until = [&](int slot, int target) {
            while (cws[slot] <= target) {
                mbar_wait(cmb[slot], cph[slot]);
                cph[slot] ^= 1;
                cws[slot] += NST;
            }
        };

        int nb[2][GOFF];
        auto prefetch = [&](int i) {
            const int c = i / TG, j = i - (i / TG) * TG;
            const int ob = (c / KSPL) * GOFF;
            #pragma unroll
            for (int k = 0; k < 2; ++k) {
                int u = t + k * 224;
                if (u < 256) {
                    int row = u >> 1;
                    #pragma unroll
                    for (int p = 0; p < GOFF; ++p) {
                        int ko = ob + p;
                        nb[k][p] = (ko < 27)
                            ? g_nbr[ko * NPTS + (tileBase + j) * BM + row] : -1;
                    }
                }
            }
        };

        auto fill_B = [&](int c2) {
            const uint32_t bb = BDBL ? bBase + (c2 & 1) * BSZ : bBase;
            const char* sh = whp + (size_t)c2 * BT;
            const char* sl = wlp + (size_t)c2 * BT;
            for (int q = t; q < BT / 16; q += 224) {
                cp16(bb + q * 16,      sh + q * 16, 16);
                cp16(bb + BT + q * 16, sl + q * 16, 16);
            }
        };

        prefetch(0);
        #pragma unroll 1
        for (int i = 0; i < TOT; ++i) {
            const int c = i / TG, j = i - c * TG;
            const int s = i % NST;
            const int kc = c % KSPL;

            wait_until(s, i - NST);
            if (i == 0) fill_B(0);
            if (!BDBL && j == 0 && c > 0) {
                // drain: all of chunk c-1's MMAs (<= i-1) must retire
                #pragma unroll
                for (int s2 = 0; s2 < NST; ++s2) wait_until(s2, i - 1);
                fill_B(c);
            }

            // A gathers into stage s
            #pragma unroll
            for (int k = 0; k < 2; ++k) {
                int u = t + k * 224;
                if (u < 256) {
                    const int row = u >> 1, half = u & 1;
                    const __nv_bfloat16* fp = half ? g_fl : g_fh;
                    const uint32_t dst = aBase + s * ASTG + half * ATILE +
                                         row * 128;
                    #pragma unroll
                    for (int p = 0; p < GOFF; ++p) {
                        const int nbv = nb[k][p];
                        const char* src = (const char*)
                            (fp + (size_t)(nbv < 0 ? 0 : nbv) * CIN + kc * 64);
                        const int sz = nbv >= 0 ? 16 : 0;
                        #pragma unroll
                        for (int s2 = 0; s2 < SUBSEG; ++s2) {
                            int g = p * SUBSEG + s2;
                            cp16(dst + (((g ^ (row & 7)) << 4)),
                                 src + s2 * 16, sz);
                        }
                    }
                }
            }
            // BDBL: refresh next chunk's B at last tile of this chunk.
            // Safe: ring wait gave commit(i-NST) >= commit(c*TG-1) (TG>=NST).
            if (BDBL && j == TG - 1 && c + 1 < NCH) fill_B(c + 1);

            cp_mbar_arrive(fmb[s]);
            if (i + 1 < TOT) prefetch(i + 1);
        }
        #pragma unroll
        for (int s = 0; s < NST; ++s) wait_until(s, TOT - 1);
    } else {
        // ======================= CONSUMER (warp 7) =======================
        uint32_t fph[NST];
        #pragma unroll
        for (int s = 0; s < NST; ++s) fph[s] = 0u;
        #pragma unroll 1
        for (int i = 0; i < TOT; ++i) {
            const int c = i / TG, j = i - c * TG;
            const int s = i % NST;
            mbar_wait(fmb[s], fph[s]);
            fph[s] ^= 1;
            fence_proxy_async_sc();
            tc_fence_after();
            if (elect_one()) {
                const uint32_t bb  = BDBL ? bBase + (c & 1) * BSZ : bBase;
                const uint32_t ab  = aBase + s * ASTG;
                uint64_t dAh = mk_desc(ab);
                uint64_t dAl = mk_desc(ab + ATILE);
                uint64_t dBh = mk_desc(bb);
                uint64_t dBl = mk_desc(bb + BT);
                const uint32_t dTm = tmem + (uint32_t)(j * COUT);
                #pragma unroll
                for (int ks = 0; ks < 4; ++ks)
                    mma_ss_bf16(dTm, dAh + ks * 2, dBh + ks * 2, IDESC,
                                (c == 0 && ks == 0) ? 0u : 1u);
                #pragma unroll
                for (int ks = 0; ks < 4; ++ks)
                    mma_ss_bf16(dTm, dAh + ks * 2, dBl + ks * 2, IDESC, 1u);
                #pragma unroll
                for (int ks = 0; ks < 4; ++ks)
                    mma_ss_bf16(dTm, dAl + ks * 2, dBh + ks * 2, IDESC, 1u);
                tc_commit(cmb[s]);
            }
        }
    }

    __syncthreads();
    tc_fence_after();

    // ---------------- epilogue ----------------
    const int grp     = wid >> 2;
    const int rw      = wid & 3;
    const int colBase = grp * CPW;

    for (int j = 0; j < TG; ++j) {
        const int tile = tileBase + j;
        const int row  = tile * BM + rw * 32 + lane;
        #pragma unroll
        for (int p = 0; p < CPW / 32; ++p) {
            uint32_t dr[32];
            ldtm_x32(dr, tmem + (uint32_t)(j * COUT + colBase + p * 32));
            tc_wait_ld();
            #pragma unroll
            for (int jj = 0; jj < 32; jj += 4) {
                float y[4];
                #pragma unroll
                for (int q = 0; q < 4; ++q) {
                    int col = colBase + p * 32 + jj + q;
                    y[q] = __uint_as_float(dr[jj + q]) + __ldg(bias + col);
                    float s = y[q], qq = y[q] * y[q];
                    #pragma unroll
                    for (int o = 16; o; o >>= 1) {
                        s  += __shfl_xor_sync(0xffffffffu, s, o);
                        qq += __shfl_xor_sync(0xffffffffu, qq, o);
                    }
                    if (lane == (col & 31)) {
                        sP[rw][col] = s;
                        sQ[rw][col] = qq;
                    }
                }
                *(float4*)(&g_conv[(size_t)row * COUT + colBase + p * 32 + jj]) =
                    make_float4(y[0], y[1], y[2], y[3]);
            }
        }
        __syncthreads();
        if (t < COUT) {
            g_part[(size_t)tile * COUT + t] =
                sP[0][t] + sP[1][t] + sP[2][t] + sP[3][t];
            g_partsq[(size_t)tile * COUT + t] =
                sQ[0][t] + sQ[1][t] + sQ[2][t] + sQ[3][t];
        }
        __syncthreads();
    }
    tc_fence_before();
    __syncthreads();
    if (wid == 0) tmem_dealloc(tmem, TG * COUT);

#else  // ------------------- scalar FFMA fallback -------------
    constexpr int BK   = (CIN < 64) ? CIN : 64;
    constexpr int KCH  = KSPL;
    constexpr int TN   = COUT / 16;
    constexpr int SEGS = BK / 4;

    extern __shared__ __align__(16) float sm[];
    float* As = sm;
    float* Bs = sm + BK * BM;
    __shared__ int sN[BM];

    const int t  = threadIdx.x;
    const int tr = t >> 4;
    const int tc = t & 15;

    for (int tile = blockIdx.x * TG; tile < (blockIdx.x + 1) * TG; ++tile) {
        const int rowBase = tile * BM;

        unsigned long long acc[8][TN/2];
        #pragma unroll
        for (int i = 0; i < 8; i++)
            #pragma unroll
            for (int j = 0; j < TN/2; j++) acc[i][j] = 0ull;

        for (int k = 0; k < 27; k++) {
            __syncthreads();
            if (t < BM) sN[t] = g_nbr[k * NPTS + rowBase + t];
            __syncthreads();
            #pragma unroll
            for (int kc = 0; kc < KCH; kc++) {
                if (kc) __syncthreads();
                #pragma unroll
                for (int f = t; f < BM * SEGS; f += 256) {
                    int row = f / SEGS;
                    int seg = f - row * SEGS;
                    int nb  = sN[row];
                    float4 v = make_float4(0.f, 0.f, 0.f, 0.f);
                    if (nb >= 0)
                        v = *reinterpret_cast<const float4*>(
                            featF + (size_t)nb * CIN + kc * BK + seg * 4);
                    int rs = row ^ ((seg & 3) << 3);
                    As[(seg*4+0)*BM + rs] = v.x;
                    As[(seg*4+1)*BM + rs] = v.y;
                    As[(seg*4+2)*BM + rs] = v.z;
                    As[(seg*4+3)*BM + rs] = v.w;
                }
                const float4* Wk = (const float4*)(
                    g_Wf + wfbase + ((size_t)(k * KCH + kc)) * BK * COUT);
                #pragma unroll
                for (int f = t; f < BK * COUT / 4; f += 256)
                    reinterpret_cast<float4*>(Bs)[f] = Wk[f];
                __syncthreads();
                #pragma unroll 8
                for (int kk = 0; kk < BK; kk++) {
                    int rbase = (tr * 8) ^ (((kk >> 2) & 3) << 3);
                    float4 a0 = *reinterpret_cast<const float4*>(&As[kk*BM + rbase]);
                    float4 a1 = *reinterpret_cast<const float4*>(&As[kk*BM + rbase + 4]);
                    unsigned long long ad[8];
                    ad[0] = pack_dup(a0.x); ad[1] = pack_dup(a0.y);
                    ad[2] = pack_dup(a0.z); ad[3] = pack_dup(a0.w);
                    ad[4] = pack_dup(a1.x); ad[5] = pack_dup(a1.y);
                    ad[6] = pack_dup(a1.z); ad[7] = pack_dup(a1.w);
                    unsigned long long bb[TN/2];
                    const ulonglong2* bp = reinterpret_cast<const ulonglong2*>(
                        &Bs[kk * COUT + tc * TN]);
                    {
                        ulonglong2 b0 = bp[0];
                        bb[0] = b0.x; bb[1] = b0.y;
                        if constexpr (TN == 8) {
                            ulonglong2 b1 = bp[1];
                            bb[2] = b1.x; bb[3] = b1.y;
                        }
                    }
                    #pragma unroll
                    for (int i = 0; i < 8; i++)
                        #pragma unroll
                        for (int j = 0; j < TN/2; j++)
                            fma2(acc[i][j], ad[i], bb[j]);
                }
            }
        }

        float bv[TN];
        #pragma unroll
        for (int j = 0; j < TN; j++) bv[j] = bias[tc * TN + j];
        float cs[TN], cq[TN];
        #pragma unroll
        for (int j = 0; j < TN; j++) { cs[j] = 0.f; cq[j] = 0.f; }

        #pragma unroll
        for (int i = 0; i < 8; i++) {
            float yv[TN];
            #pragma unroll
            for (int j = 0; j < TN/2; j++) {
                float2 p = unpack2(acc[i][j]);
                yv[2*j]   = p.x + bv[2*j];
                yv[2*j+1] = p.y + bv[2*j+1];
            }
            #pragma unroll
            for (int j = 0; j < TN; j++) { cs[j] += yv[j]; cq[j] += yv[j]*yv[j]; }
            int row = rowBase + tr * 8 + i;
            #pragma unroll
            for (int j = 0; j < TN; j += 4) {
                float4 o = make_float4(yv[j], yv[j+1], yv[j+2], yv[j+3]);
                *reinterpret_cast<float4*>(
                    &g_conv[(size_t)row * COUT + tc * TN + j]) = o;
            }
        }

        __syncthreads();
        #pragma unroll
        for (int j = 0; j < TN; j++) As[tr * COUT + tc * TN + j] = cs[j];
        __syncthreads();
        if (t < COUT) {
            float s = 0.f;
            #pragma unroll
            for (int rr = 0; rr < 16; rr++) s += As[rr * COUT + t];
            g_part[(size_t)tile * COUT + t] = s;
        }
        __syncthreads();
        #pragma unroll
        for (int j = 0; j < TN; j++) As[tr * COUT + tc * TN + j] = cq[j];
        __syncthreads();
        if (t < COUT) {
            float s = 0.f;
            #pragma unroll
            for (int rr = 0; rr < 16; rr++) s += As[rr * COUT + t];
            g_partsq[(size_t)tile * COUT + t] = s;
        }
        __syncthreads();
    }
#endif
}

// ---------------- BN statistics ----------------
__global__ void bn_reduce_kernel(const float* __restrict__ gamma,
                                 const float* __restrict__ beta, int cout) {
    __shared__ float ss[256], sq[256];
    int c = blockIdx.x;
    int t = threadIdx.x;
    float s = 0.f, q = 0.f;
    for (int b = t; b < NBLK; b += 256) {
        s += g_part[b * cout + c];
        q += g_partsq[b * cout + c];
    }
    ss[t] = s; sq[t] = q;
    __syncthreads();
    for (int o = 128; o > 0; o >>= 1) {
        if (t < o) { ss[t] += ss[t + o]; sq[t] += sq[t + o]; }
        __syncthreads();
    }
    if (t == 0) {
        float mean = ss[0] * INVN;
        float var  = sq[0] * INVN - mean * mean;
        float sc   = gamma[c] * rsqrtf(var + BN_EPS);
        g_scale[c] = sc;
        g_shift[c] = beta[c] - mean * sc;
    }
}

// ---------------- BN apply + ReLU ----------------
template <int COUT>
__global__ void bnrelu_kernel() {
    int i = blockIdx.x * 256 + threadIdx.x;
    int c = i & (COUT - 1);
    float v = fmaf(g_conv[i], g_scale[c], g_shift[c]);
    v = v > 0.f ? v : 0.f;
#if !HAS_TCGEN05
    g_feat[i] = v;
#endif
    __nv_bfloat16 h = __float2bfloat16(v);
    g_fh[i] = h;
    g_fl[i] = __float2bfloat16(v - __bfloat162float(h));
}

// ---------------- final dense scatter ----------------
__global__ void final_out_kernel(float* __restrict__ out) {
    int idx = blockIdx.x * 256 + threadIdx.x;
    int lin = idx % VOLPB;
    int bc  = idx / VOLPB;
    int c = bc & 63;
    int b = bc >> 6;
    int row = g_map[b * VOLPB + lin];
    float v = 0.f;
    if (row >= 0) {
        float y = fmaf(g_conv[(size_t)row * 64 + c], g_scale[c], g_shift[c]);
        v = y > 0.f ? y : 0.f;
    }
    out[idx] = v;
}

// ---------------- launch ----------------
extern "C" void kernel_launch(void* const* d_in, const int* in_sizes, int n_in,
                              void* d_out, int out_size) {
    (void)in_sizes; (void)out_size;
    int base = (n_in >= 15) ? 3 : 2;
    const float* features = (const float*)d_in[0];
    const int*   indices  = (const int*)d_in[1];
    const float* W0  = (const float*)d_in[base + 0];
    const float* b0  = (const float*)d_in[base + 1];
    const float* ga0 = (const float*)d_in[base + 2];
    const float* be0 = (const float*)d_in[base + 3];
    const float* W1  = (const float*)d_in[base + 4];
    const float* b1  = (const float*)d_in[base + 5];
    const float* ga1 = (const float*)d_in[base + 6];
    const float* be1 = (const float*)d_in[base + 7];
    const float* W2  = (const float*)d_in[base + 8];
    const float* b2  = (const float*)d_in[base + 9];
    const float* ga2 = (const float*)d_in[base + 10];
    const float* be2 = (const float*)d_in[base + 11];
    float* out = (float*)d_out;

    float* featp = nullptr;
    cudaGetSymbolAddress((void**)&featp, g_feat);

    // smem: NST*32KB (A ring) + B bufs + 1KB pad ; all <= ~97KB -> 2 CTAs/SM
    constexpr int SMC0 = 2 * 32768 + 2 * (2 * 64  * 128) + 1024;  // 99328
    constexpr int SMC1 = 2 * 32768 + 1 * (2 * 128 * 128) + 1024;  // 99328
    constexpr int SMC2 = 2 * 32768 + 2 * (2 * 64  * 128) + 1024;  // 99328
    cudaFuncSetAttribute(conv_kernel<16, 64, 4, 1, 4, 7, 2, true>,
                         cudaFuncAttributeMaxDynamicSharedMemorySize, SMC0);
    cudaFuncSetAttribute(conv_kernel<64, 128, 1, 1, 2, 27, 2, false>,
                         cudaFuncAttributeMaxDynamicSharedMemorySize, SMC1);
    cudaFuncSetAttribute(conv_kernel<128, 64, 1, 2, 4, 54, 2, true>,
                         cudaFuncAttributeMaxDynamicSharedMemorySize, SMC2);

    prep0_kernel<<<NVOX / 256, 256>>>(W0, W1, W2);
    prep1_kernel<<<NPTS * 16 / 256, 256>>>(indices, features);
    build_nbr_kernel<<<27 * NPTS / 256, 256>>>(indices);

    // layer 0: 16 -> 64 (TG=4 -> 864 CTAs, 28 items, B dbl)
    conv_kernel<16, 64, 4, 1, 4, 7, 2, true><<<NBLK / 4, 256, SMC0>>>(
        features, b0, WH0, WF0);
    bn_reduce_kernel<<<64, 256>>>(ga0, be0, 64);
    bnrelu_kernel<64><<<NPTS * 64 / 256, 256>>>();

    // layer 1: 64 -> 128 (TG=2 -> 1728 CTAs, 54 items, B single + drains)
    conv_kernel<64, 128, 1, 1, 2, 27, 2, false><<<NBLK / 2, 256, SMC1>>>(
        featp, b1, WH1, WF1);
    bn_reduce_kernel<<<128, 256>>>(ga1, be1, 128);
    bnrelu_kernel<128><<<NPTS * 128 / 256, 256>>>();

    // layer 2: 128 -> 64 (TG=4 -> 864 CTAs, 216 items, B dbl: drain-free)
    conv_kernel<128, 64, 1, 2, 4, 54, 2, true><<<NBLK / 4, 256, SMC2>>>(
        featp, b2, WH2, WF2);
    bn_reduce_kernel<<<64, 256>>>(ga2, be2, 64);

    final_out_kernel<<<(BATCH * 64 * VOLPB) / 256, 256>>>(out);
}